// round 2
// baseline (speedup 1.0000x reference)
#include <cuda_runtime.h>
#include <math.h>

#define NN 8192
#define DD 64
#define EE 262144
#define HSIZE (1u << 20)
#define HMASK (HSIZE - 1u)
#define HEMPTY 0xFFFFFFFFFFFFFFFFull

#define BQ 64
#define BK 64
#define SQ_STRIDE 132   // 128 + 4 pad, rows stay 16B aligned
#define SP_STRIDE 68    // 64 + 4 pad

// ---- static device scratch (no allocations allowed) ----
__device__ float g_G[NN * 128];          // [c | s] per node, 4 MB (L2-resident)
__device__ float g_rsum[NN];
__device__ float g_accm[NN * DD];
__device__ float g_accp[NN * DD];
__device__ unsigned long long g_hash[HSIZE];  // 8 MB dedupe table
__device__ float g_escore[EE];
__device__ int   g_ne;
__device__ int   g_csrc[EE];
__device__ int   g_cdst[EE];
__device__ float g_cbias[EE];
__device__ float g_wsum4[4];
__device__ float g_bsum;
__device__ int   g_idx64;                // 1 if edge_index buffer is int64

// ---- detect edge_index dtype: int64 little-endian of small values has odd words == 0 ----
__global__ void k_detect(const unsigned* __restrict__ p) {
    if (threadIdx.x == 0) {
        int all0 = 1;
        #pragma unroll
        for (int i = 1; i < 64; i += 2)
            if (p[i] != 0u) all0 = 0;
        g_idx64 = all0;
    }
}

// ---- collapse Linear(edge_attr).sum(-1) to a 4-vector + scalar ----
__global__ void k_wsum(const float* __restrict__ W, const float* __restrict__ b) {
    __shared__ float red[5][64];
    int t = threadIdx.x;  // 64 threads
    red[0][t] = W[t * 4 + 0];
    red[1][t] = W[t * 4 + 1];
    red[2][t] = W[t * 4 + 2];
    red[3][t] = W[t * 4 + 3];
    red[4][t] = b[t];
    __syncthreads();
    if (t < 5) {
        float s = 0.f;
        #pragma unroll
        for (int i = 0; i < 64; i++) s += red[t][i];
        if (t < 4) g_wsum4[t] = s;
        else       g_bsum = s;
    }
}

// ---- G = [mag*cos(phase) | mag*sin(phase)] ----
__global__ void k_prep(const float* __restrict__ mag, const float* __restrict__ phase) {
    int idx = blockIdx.x * blockDim.x + threadIdx.x;
    if (idx >= NN * DD) return;
    int i = idx >> 6, d = idx & 63;
    float m = mag[idx], ph = phase[idx];
    float sv, cv;
    sincosf(ph, &sv, &cv);
    g_G[i * 128 + d]      = m * cv;
    g_G[i * 128 + 64 + d] = m * sv;
}

__global__ void k_clear() {
    unsigned idx = blockIdx.x * blockDim.x + threadIdx.x;
    if (idx < HSIZE) g_hash[idx] = HEMPTY;
    if (idx == 0) g_ne = 0;
}

// ---- edge scores + lock-free dedupe (last edge index wins, JAX scatter-set order) ----
__global__ void k_edge(const void* __restrict__ eiv, const float* __restrict__ ea) {
    int e = blockIdx.x * blockDim.x + threadIdx.x;
    if (e >= EE) return;
    int src, dst;
    if (g_idx64) {
        const long long* ei = (const long long*)eiv;
        src = (int)ei[e];
        dst = (int)ei[EE + e];
    } else {
        const int* ei = (const int*)eiv;
        src = ei[e];
        dst = ei[EE + e];
    }
    src &= 8191; dst &= 8191;   // hard bound: wrong answers beat crashes

    float score = ea[4 * e + 0] * g_wsum4[0] + ea[4 * e + 1] * g_wsum4[1]
                + ea[4 * e + 2] * g_wsum4[2] + ea[4 * e + 3] * g_wsum4[3] + g_bsum;
    g_escore[e] = score;

    unsigned key = ((unsigned)src << 13) | (unsigned)dst;  // 26 bits
    unsigned long long entry = ((unsigned long long)key << 32) | (unsigned)e;
    unsigned h = key * 0x9E3779B1u;
    h ^= h >> 15;
    h &= HMASK;
    for (;;) {
        unsigned long long cur = g_hash[h];
        if (cur == HEMPTY) {
            unsigned long long prev = atomicCAS(&g_hash[h], HEMPTY, entry);
            if (prev == HEMPTY) break;
            cur = prev;
        }
        if ((unsigned)(cur >> 32) == key) {
            atomicMax(&g_hash[h], entry);  // same key: highest e wins
            break;
        }
        h = (h + 1) & HMASK;
    }
}

__global__ void k_compact() {
    unsigned idx = blockIdx.x * blockDim.x + threadIdx.x;
    if (idx >= HSIZE) return;
    unsigned long long cur = g_hash[idx];
    if (cur == HEMPTY) return;
    unsigned key = (unsigned)(cur >> 32);
    unsigned e   = (unsigned)(cur & 0xFFFFFFFFu);
    int pos = atomicAdd(&g_ne, 1);
    g_csrc[pos]  = (int)(key >> 13);
    g_cdst[pos]  = (int)(key & 8191u);
    g_cbias[pos] = g_escore[e];
}

// ---- fused dense attention (no bias): rowsum + P@[mag|phase], no normalization yet ----
__global__ void __launch_bounds__(256, 1)
k_attn(const float* __restrict__ mag, const float* __restrict__ phase) {
    extern __shared__ float sm[];
    float* sQ   = sm;                        // [BQ][SQ_STRIDE]
    float* sK   = sQ + BQ * SQ_STRIDE;       // [BK][SQ_STRIDE]
    float* sV   = sK + BK * SQ_STRIDE;       // [BK][SQ_STRIDE] = [mag | phase]
    float* sP   = sV + BK * SQ_STRIDE;       // [BQ][SP_STRIDE]
    float* srow = sP + BQ * SP_STRIDE;       // [BQ]

    int tid = threadIdx.x;
    int tx = tid & 15, ty = tid >> 4;
    int qbase = blockIdx.x * BQ;
    int q0 = ty * 4;
    int d0 = tx * 8;

    for (int idx = tid; idx < BQ * 128; idx += 256) {
        int q = idx >> 7, kk = idx & 127;
        sQ[q * SQ_STRIDE + kk] = g_G[(qbase + q) * 128 + kk];
    }
    if (tid < BQ) srow[tid] = 0.f;

    float oacc[4][8];
    #pragma unroll
    for (int i = 0; i < 4; i++)
        #pragma unroll
        for (int j = 0; j < 8; j++) oacc[i][j] = 0.f;
    float rs[4] = {0.f, 0.f, 0.f, 0.f};

    __syncthreads();

    for (int kb = 0; kb < NN; kb += BK) {
        // stage K (G rows) and V ([mag|phase]) tiles
        for (int idx = tid; idx < BK * 128; idx += 256) {
            int k = idx >> 7, kk = idx & 127;
            sK[k * SQ_STRIDE + kk] = g_G[(kb + k) * 128 + kk];
            sV[k * SQ_STRIDE + kk] = (kk < 64) ? mag[(kb + k) * 64 + kk]
                                               : phase[(kb + k) * 64 + kk - 64];
        }
        __syncthreads();

        // S = Gq . Gk^T  (thread tile 4q x 4k, k interleaved by 16 for bank spread)
        float acc[4][4];
        #pragma unroll
        for (int i = 0; i < 4; i++)
            #pragma unroll
            for (int j = 0; j < 4; j++) acc[i][j] = 0.f;

        #pragma unroll 4
        for (int kk = 0; kk < 128; kk += 4) {
            float4 qa[4], ka[4];
            #pragma unroll
            for (int i = 0; i < 4; i++)
                qa[i] = *(const float4*)&sQ[(q0 + i) * SQ_STRIDE + kk];
            #pragma unroll
            for (int j = 0; j < 4; j++)
                ka[j] = *(const float4*)&sK[(tx + 16 * j) * SQ_STRIDE + kk];
            #pragma unroll
            for (int i = 0; i < 4; i++)
                #pragma unroll
                for (int j = 0; j < 4; j++) {
                    acc[i][j] += qa[i].x * ka[j].x;
                    acc[i][j] += qa[i].y * ka[j].y;
                    acc[i][j] += qa[i].z * ka[j].z;
                    acc[i][j] += qa[i].w * ka[j].w;
                }
        }

        // exp (no max-sub needed: max score ~55 << fp32 overflow), stash P, track rowsum
        #pragma unroll
        for (int i = 0; i < 4; i++)
            #pragma unroll
            for (int j = 0; j < 4; j++) {
                float p = __expf(acc[i][j]);
                rs[i] += p;
                sP[(q0 + i) * SP_STRIDE + tx + 16 * j] = p;
            }
        __syncthreads();

        // O += P . V   (thread tile 4q x 8d)
        #pragma unroll 2
        for (int k = 0; k < BK; k++) {
            float4 v0 = *(const float4*)&sV[k * SQ_STRIDE + d0];
            float4 v1 = *(const float4*)&sV[k * SQ_STRIDE + d0 + 4];
            #pragma unroll
            for (int i = 0; i < 4; i++) {
                float p = sP[(q0 + i) * SP_STRIDE + k];
                oacc[i][0] += p * v0.x; oacc[i][1] += p * v0.y;
                oacc[i][2] += p * v0.z; oacc[i][3] += p * v0.w;
                oacc[i][4] += p * v1.x; oacc[i][5] += p * v1.y;
                oacc[i][6] += p * v1.z; oacc[i][7] += p * v1.w;
            }
        }
        __syncthreads();
    }

    #pragma unroll
    for (int i = 0; i < 4; i++) atomicAdd(&srow[q0 + i], rs[i]);
    __syncthreads();
    if (tid < BQ) g_rsum[qbase + tid] = srow[tid];

    #pragma unroll
    for (int i = 0; i < 4; i++) {
        int q = qbase + q0 + i;
        #pragma unroll
        for (int j = 0; j < 8; j++) {
            int d = d0 + j;
            if (d < 64) g_accm[q * 64 + d] = oacc[i][j];
            else        g_accp[q * 64 + d - 64] = oacc[i][j];
        }
    }
}

// ---- sparse bias corrections: one warp per deduped edge ----
__global__ void k_corr(const float* __restrict__ mag, const float* __restrict__ phase) {
    int w = (blockIdx.x * blockDim.x + threadIdx.x) >> 5;
    int lane = threadIdx.x & 31;
    if (w >= g_ne) return;
    int src = g_csrc[w], dst = g_cdst[w];
    float bias = g_cbias[w];

    const float4* Gs = (const float4*)(g_G + src * 128);
    const float4* Gd = (const float4*)(g_G + dst * 128);
    float4 a = Gs[lane], q = Gd[lane];
    float s = a.x * q.x + a.y * q.y + a.z * q.z + a.w * q.w;
    #pragma unroll
    for (int off = 16; off; off >>= 1) s += __shfl_xor_sync(0xffffffffu, s, off);

    float delta = __expf(s) * expm1f(bias);  // exp(s+bias) - exp(s), exact-set semantics
    if (lane == 0) atomicAdd(&g_rsum[src], delta);
    atomicAdd(&g_accm[src * 64 + lane],      delta * mag[dst * 64 + lane]);
    atomicAdd(&g_accm[src * 64 + lane + 32], delta * mag[dst * 64 + lane + 32]);
    atomicAdd(&g_accp[src * 64 + lane],      delta * phase[dst * 64 + lane]);
    atomicAdd(&g_accp[src * 64 + lane + 32], delta * phase[dst * 64 + lane + 32]);
}

// ---- normalize into output: [new_mag (N*D) | new_phase (N*D)] ----
__global__ void k_norm(float* __restrict__ out) {
    int idx = blockIdx.x * blockDim.x + threadIdx.x;
    if (idx >= NN * DD) return;
    float inv = 1.f / g_rsum[idx >> 6];
    out[idx]           = g_accm[idx] * inv;
    out[NN * DD + idx] = g_accp[idx] * inv;
}

extern "C" void kernel_launch(void* const* d_in, const int* in_sizes, int n_in,
                              void* d_out, int out_size) {
    const float* mag   = (const float*)d_in[0];
    const float* phase = (const float*)d_in[1];
    const void*  ei    = d_in[2];
    const float* ea    = (const float*)d_in[3];
    const float* W     = (const float*)d_in[4];
    const float* b     = (const float*)d_in[5];
    float* out = (float*)d_out;

    size_t smem = (size_t)(3 * BQ * SQ_STRIDE + BQ * SP_STRIDE + BQ) * sizeof(float);
    cudaFuncSetAttribute(k_attn, cudaFuncAttributeMaxDynamicSharedMemorySize, (int)smem);

    k_detect<<<1, 32>>>((const unsigned*)ei);
    k_wsum<<<1, 64>>>(W, b);
    k_prep<<<(NN * DD + 255) / 256, 256>>>(mag, phase);
    k_clear<<<(HSIZE + 255) / 256, 256>>>();
    k_edge<<<(EE + 255) / 256, 256>>>(ei, ea);
    k_compact<<<(HSIZE + 255) / 256, 256>>>();
    k_attn<<<NN / BQ, 256, smem>>>(mag, phase);
    k_corr<<<EE / 8, 256>>>(mag, phase);   // 8 warps/CTA, one warp per edge
    k_norm<<<(NN * DD + 255) / 256, 256>>>(out);
}

// round 4
// speedup vs baseline: 4.0126x; 4.0126x over previous
#include <cuda_runtime.h>
#include <cuda_bf16.h>
#include <math.h>

#define NN 8192
#define DD 64
#define EE 262144
#define HSIZE (1u << 20)
#define HMASK (HSIZE - 1u)
#define HEMPTY 0xFFFFFFFFFFFFFFFFull

// ===================== base-ISA tensor primitives =====================
#define MMA_BF16(C, A, B0, B1) \
    asm volatile("mma.sync.aligned.m16n8k16.row.col.f32.bf16.bf16.f32 " \
        "{%0,%1,%2,%3}, {%4,%5,%6,%7}, {%8,%9}, {%0,%1,%2,%3};" \
        : "+f"((C)[0]), "+f"((C)[1]), "+f"((C)[2]), "+f"((C)[3]) \
        : "r"((A)[0]), "r"((A)[1]), "r"((A)[2]), "r"((A)[3]), "r"(B0), "r"(B1))

#define LDSM4(R, addr) \
    asm volatile("ldmatrix.sync.aligned.m8n8.x4.shared.b16 {%0,%1,%2,%3}, [%4];" \
        : "=r"((R)[0]), "=r"((R)[1]), "=r"((R)[2]), "=r"((R)[3]) : "r"(addr))

#define CPA16(dst, src) \
    asm volatile("cp.async.cg.shared.global [%0], [%1], 16;" :: "r"(dst), "l"(src))
#define CP_COMMIT() asm volatile("cp.async.commit_group;" ::: "memory")
#define CP_WAIT0()  asm volatile("cp.async.wait_group 0;" ::: "memory")

__device__ __forceinline__ unsigned pack_bf16x2(float lo, float hi) {
    unsigned r;
    asm("cvt.rn.bf16x2.f32 %0, %1, %2;" : "=r"(r) : "f"(hi), "f"(lo));  // first src = upper
    return r;
}

// ===================== static device scratch =====================
__device__ float g_G[NN * 128];                 // fp32 (for k_corr)
__device__ __nv_bfloat16 g_Ghi[NN * 128];       // bf16 hi split of G
__device__ __nv_bfloat16 g_Glo[NN * 128];       // bf16 lo split
__device__ __nv_bfloat16 g_Vth[128 * NN];       // V^T = [mag|phase]^T, hi
__device__ __nv_bfloat16 g_Vtl[128 * NN];       // lo
__device__ float g_rsum[NN];
__device__ float g_accm[NN * DD];
__device__ float g_accp[NN * DD];
__device__ unsigned long long g_hash[HSIZE];
__device__ float g_escore[EE];
__device__ int   g_ne;
__device__ int   g_csrc[EE];
__device__ int   g_cdst[EE];
__device__ float g_cbias[EE];
__device__ float g_wsum4[4];
__device__ float g_bsum;
__device__ int   g_idx64;

// ===================== small kernels =====================
__global__ void k_detect(const unsigned* __restrict__ p) {
    if (threadIdx.x == 0) {
        int all0 = 1;
        #pragma unroll
        for (int i = 1; i < 64; i += 2)
            if (p[i] != 0u) all0 = 0;
        g_idx64 = all0;
    }
}

__global__ void k_wsum(const float* __restrict__ W, const float* __restrict__ b) {
    __shared__ float red[5][64];
    int t = threadIdx.x;
    red[0][t] = W[t * 4 + 0];
    red[1][t] = W[t * 4 + 1];
    red[2][t] = W[t * 4 + 2];
    red[3][t] = W[t * 4 + 3];
    red[4][t] = b[t];
    __syncthreads();
    if (t < 5) {
        float s = 0.f;
        #pragma unroll
        for (int i = 0; i < 64; i++) s += red[t][i];
        if (t < 4) g_wsum4[t] = s;
        else       g_bsum = s;
    }
}

__global__ void k_prep(const float* __restrict__ mag, const float* __restrict__ phase) {
    int idx = blockIdx.x * blockDim.x + threadIdx.x;
    if (idx >= NN * DD) return;
    int i = idx >> 6, d = idx & 63;
    float m = mag[idx], ph = phase[idx];
    float sv, cv;
    sincosf(ph, &sv, &cv);
    float gc = m * cv, gs = m * sv;
    g_G[i * 128 + d]      = gc;
    g_G[i * 128 + 64 + d] = gs;
    __nv_bfloat16 hc = __float2bfloat16(gc);
    __nv_bfloat16 hs = __float2bfloat16(gs);
    g_Ghi[i * 128 + d]      = hc;
    g_Ghi[i * 128 + 64 + d] = hs;
    g_Glo[i * 128 + d]      = __float2bfloat16(gc - __bfloat162float(hc));
    g_Glo[i * 128 + 64 + d] = __float2bfloat16(gs - __bfloat162float(hs));
}

// transpose [k][d] -> Vt[d][k] with bf16 hi/lo split (32x32 tiles)
__global__ void k_prepv(const float* __restrict__ mag, const float* __restrict__ phase) {
    __shared__ float t[32][33];
    int k0 = blockIdx.x * 32;
    int d0 = blockIdx.y * 32;
    int tx = threadIdx.x & 31, ty = threadIdx.x >> 5;  // 32 x 8
    const float* src = (d0 < 64) ? mag : phase;
    int dcol = (d0 < 64) ? d0 : d0 - 64;
    #pragma unroll
    for (int r = 0; r < 4; r++) {
        int k = k0 + ty + r * 8;
        t[ty + r * 8][tx] = src[k * 64 + dcol + tx];
    }
    __syncthreads();
    #pragma unroll
    for (int r = 0; r < 4; r++) {
        int d = d0 + ty + r * 8;
        float v = t[tx][ty + r * 8];
        __nv_bfloat16 h = __float2bfloat16(v);
        g_Vth[d * NN + k0 + tx] = h;
        g_Vtl[d * NN + k0 + tx] = __float2bfloat16(v - __bfloat162float(h));
    }
}

__global__ void k_clear() {
    unsigned idx = blockIdx.x * blockDim.x + threadIdx.x;
    if (idx < HSIZE) g_hash[idx] = HEMPTY;
    if (idx < NN * DD) { g_accm[idx] = 0.f; g_accp[idx] = 0.f; }
    if (idx < NN) g_rsum[idx] = 0.f;
    if (idx == 0) g_ne = 0;
}

__global__ void k_edge(const void* __restrict__ eiv, const float* __restrict__ ea) {
    int e = blockIdx.x * blockDim.x + threadIdx.x;
    if (e >= EE) return;
    int src, dst;
    if (g_idx64) {
        const long long* ei = (const long long*)eiv;
        src = (int)ei[e];
        dst = (int)ei[EE + e];
    } else {
        const int* ei = (const int*)eiv;
        src = ei[e];
        dst = ei[EE + e];
    }
    src &= 8191; dst &= 8191;

    float score = ea[4 * e + 0] * g_wsum4[0] + ea[4 * e + 1] * g_wsum4[1]
                + ea[4 * e + 2] * g_wsum4[2] + ea[4 * e + 3] * g_wsum4[3] + g_bsum;
    g_escore[e] = score;

    unsigned key = ((unsigned)src << 13) | (unsigned)dst;
    unsigned long long entry = ((unsigned long long)key << 32) | (unsigned)e;
    unsigned h = key * 0x9E3779B1u;
    h ^= h >> 15;
    h &= HMASK;
    for (;;) {
        unsigned long long cur = g_hash[h];
        if (cur == HEMPTY) {
            unsigned long long prev = atomicCAS(&g_hash[h], HEMPTY, entry);
            if (prev == HEMPTY) break;
            cur = prev;
        }
        if ((unsigned)(cur >> 32) == key) {
            atomicMax(&g_hash[h], entry);
            break;
        }
        h = (h + 1) & HMASK;
    }
}

__global__ void k_compact() {
    unsigned idx = blockIdx.x * blockDim.x + threadIdx.x;
    if (idx >= HSIZE) return;
    unsigned long long cur = g_hash[idx];
    if (cur == HEMPTY) return;
    unsigned key = (unsigned)(cur >> 32);
    unsigned e   = (unsigned)(cur & 0xFFFFFFFFu);
    int pos = atomicAdd(&g_ne, 1);
    g_csrc[pos]  = (int)(key >> 13);
    g_cdst[pos]  = (int)(key & 8191u);
    g_cbias[pos] = g_escore[e];
}

// ===================== mma.sync flash attention =====================
// grid=128: qb = bid>>1 (128 q rows), ks = bid&1 (split-K half of 4096 keys)
// smem (bytes):  Q rows 272B (128+8 halves), Vt rows 144B (64+8 halves)
#define QSTR 272
#define VSTR 144
#define SQH  0
#define SQL  34816
#define BUF0 69632
#define BUFS 71680
#define KH_O 0
#define KL_O 17408
#define VH_O 34816
#define VL_O 53248
#define SMEMSZ (BUF0 + 2 * BUFS)   // 212992
#define NITER 64

__global__ void __launch_bounds__(256, 1)
k_attn() {
    extern __shared__ __align__(1024) char smem[];
    unsigned sb;
    asm("{ .reg .u64 t; cvta.to.shared.u64 t, %1; cvt.u32.u64 %0, t; }"
        : "=r"(sb) : "l"(smem));

    const int tid = threadIdx.x;
    const int lane = tid & 31;
    const int wid = tid >> 5;
    const int qb = blockIdx.x >> 1;
    const int ks = blockIdx.x & 1;
    const int m0 = wid * 16;

    // ---- prologue: Q tile (hi+lo) via cp.async ----
    {
        const __nv_bfloat16* ghq = g_Ghi + (qb * 128) * 128;
        const __nv_bfloat16* glq = g_Glo + (qb * 128) * 128;
        for (int i = tid; i < 2048; i += 256) {
            int r = i >> 4, c = i & 15;
            unsigned d = sb + SQH + r * QSTR + c * 16;
            CPA16(d, (const char*)(ghq + r * 128 + c * 8));
            unsigned d2 = sb + SQL + r * QSTR + c * 16;
            CPA16(d2, (const char*)(glq + r * 128 + c * 8));
        }
    }
    // ---- tile 0 K/V ----
    {
        int kbase = ks * 4096;
        unsigned bo = sb + BUF0;
        for (int i = tid; i < 1024; i += 256) {
            int r = i >> 4, c = i & 15;
            CPA16(bo + KH_O + r * QSTR + c * 16, (const char*)(g_Ghi + (kbase + r) * 128 + c * 8));
            CPA16(bo + KL_O + r * QSTR + c * 16, (const char*)(g_Glo + (kbase + r) * 128 + c * 8));
        }
        for (int i = tid; i < 1024; i += 256) {
            int d = i >> 3, c = i & 7;
            CPA16(bo + VH_O + d * VSTR + c * 16, (const char*)(g_Vth + d * NN + kbase + c * 8));
            CPA16(bo + VL_O + d * VSTR + c * 16, (const char*)(g_Vtl + d * NN + kbase + c * 8));
        }
    }
    CP_COMMIT();
    CP_WAIT0();
    __syncthreads();

    // per-thread ldmatrix address components
    const unsigned aoff = (unsigned)(m0 + (lane & 15)) * QSTR + (unsigned)(lane >> 4) * 16;
    const unsigned brow = (unsigned)((lane & 7) + ((lane >> 4) << 3));
    const unsigned bc16 = (unsigned)((lane >> 3) & 1) * 16;
    const unsigned kboff = brow * QSTR + bc16;
    const unsigned vboff = brow * VSTR + bc16;

    float O[16][4];
    #pragma unroll
    for (int j = 0; j < 16; j++)
        #pragma unroll
        for (int i = 0; i < 4; i++) O[j][i] = 0.f;
    float rs_lo = 0.f, rs_hi = 0.f;

    for (int it = 0; it < NITER; it++) {
        unsigned cur = sb + BUF0 + (unsigned)(it & 1) * BUFS;

        // prefetch next tile
        if (it + 1 < NITER) {
            int kbase = ks * 4096 + (it + 1) * 64;
            unsigned bo = sb + BUF0 + (unsigned)((it + 1) & 1) * BUFS;
            for (int i = tid; i < 1024; i += 256) {
                int r = i >> 4, c = i & 15;
                CPA16(bo + KH_O + r * QSTR + c * 16, (const char*)(g_Ghi + (kbase + r) * 128 + c * 8));
                CPA16(bo + KL_O + r * QSTR + c * 16, (const char*)(g_Glo + (kbase + r) * 128 + c * 8));
            }
            for (int i = tid; i < 1024; i += 256) {
                int d = i >> 3, c = i & 7;
                CPA16(bo + VH_O + d * VSTR + c * 16, (const char*)(g_Vth + d * NN + kbase + c * 8));
                CPA16(bo + VL_O + d * VSTR + c * 16, (const char*)(g_Vtl + d * NN + kbase + c * 8));
            }
        }
        CP_COMMIT();

        // ---- S = Qhi.Khi + Qhi.Klo + Qlo.Khi  (m16 x n64, k=128) ----
        float S[8][4];
        #pragma unroll
        for (int j = 0; j < 8; j++)
            #pragma unroll
            for (int i = 0; i < 4; i++) S[j][i] = 0.f;

        #pragma unroll
        for (int kk = 0; kk < 8; kk++) {
            unsigned k2 = kk * 32;  // 16 halves * 2B
            unsigned qh[4], ql[4];
            LDSM4(qh, sb + SQH + aoff + k2);
            LDSM4(ql, sb + SQL + aoff + k2);
            #pragma unroll
            for (int nt = 0; nt < 4; nt++) {
                unsigned kh[4], kl[4];
                unsigned nbase = (unsigned)(nt * 16) * QSTR;
                LDSM4(kh, cur + KH_O + nbase + kboff + k2);
                LDSM4(kl, cur + KL_O + nbase + kboff + k2);
                MMA_BF16(S[2 * nt],     qh, kh[0], kh[1]);
                MMA_BF16(S[2 * nt],     qh, kl[0], kl[1]);
                MMA_BF16(S[2 * nt],     ql, kh[0], kh[1]);
                MMA_BF16(S[2 * nt + 1], qh, kh[2], kh[3]);
                MMA_BF16(S[2 * nt + 1], qh, kl[2], kl[3]);
                MMA_BF16(S[2 * nt + 1], ql, kh[2], kh[3]);
            }
        }

        // ---- P = exp(S); rowsum; repack C-frag -> A-frag (hi/lo) ----
        unsigned AH[4][4], AL[4][4];
        #pragma unroll
        for (int j = 0; j < 8; j++) {
            float e0 = __expf(S[j][0]);
            float e1 = __expf(S[j][1]);
            float e2 = __expf(S[j][2]);
            float e3 = __expf(S[j][3]);
            rs_lo += e0 + e1;
            rs_hi += e2 + e3;
            float h0 = __bfloat162float(__float2bfloat16(e0));
            float h1 = __bfloat162float(__float2bfloat16(e1));
            float h2 = __bfloat162float(__float2bfloat16(e2));
            float h3 = __bfloat162float(__float2bfloat16(e3));
            int c = j >> 1, o = (j & 1) * 2;
            AH[c][o]     = pack_bf16x2(h0, h1);
            AH[c][o + 1] = pack_bf16x2(h2, h3);
            AL[c][o]     = pack_bf16x2(e0 - h0, e1 - h1);
            AL[c][o + 1] = pack_bf16x2(e2 - h2, e3 - h3);
        }

        // ---- O += Phi.Vhi + Phi.Vlo + Plo.Vhi  (m16 x n128, k=64) ----
        #pragma unroll
        for (int c = 0; c < 4; c++) {
            unsigned k2 = c * 32;
            #pragma unroll
            for (int nt = 0; nt < 8; nt++) {
                unsigned vh[4], vl[4];
                unsigned nbase = (unsigned)(nt * 16) * VSTR;
                LDSM4(vh, cur + VH_O + nbase + vboff + k2);
                LDSM4(vl, cur + VL_O + nbase + vboff + k2);
                MMA_BF16(O[2 * nt],     AH[c], vh[0], vh[1]);
                MMA_BF16(O[2 * nt],     AH[c], vl[0], vl[1]);
                MMA_BF16(O[2 * nt],     AL[c], vh[0], vh[1]);
                MMA_BF16(O[2 * nt + 1], AH[c], vh[2], vh[3]);
                MMA_BF16(O[2 * nt + 1], AH[c], vl[2], vl[3]);
                MMA_BF16(O[2 * nt + 1], AL[c], vh[2], vh[3]);
            }
        }

        CP_WAIT0();
        __syncthreads();
    }

    // ---- rowsum reduce within quad, write ----
    rs_lo += __shfl_xor_sync(0xffffffffu, rs_lo, 1);
    rs_lo += __shfl_xor_sync(0xffffffffu, rs_lo, 2);
    rs_hi += __shfl_xor_sync(0xffffffffu, rs_hi, 1);
    rs_hi += __shfl_xor_sync(0xffffffffu, rs_hi, 2);
    int r0 = qb * 128 + m0 + (lane >> 2);
    if ((lane & 3) == 0) {
        atomicAdd(&g_rsum[r0], rs_lo);
        atomicAdd(&g_rsum[r0 + 8], rs_hi);
    }

    // ---- O writeback (split-K atomics) ----
    #pragma unroll
    for (int j = 0; j < 16; j++) {
        int n = 8 * j + 2 * (lane & 3);
        float* b0 = (n < 64) ? &g_accm[r0 * 64 + n] : &g_accp[r0 * 64 + n - 64];
        float* b1 = (n < 64) ? &g_accm[(r0 + 8) * 64 + n] : &g_accp[(r0 + 8) * 64 + n - 64];
        atomicAdd(b0,     O[j][0]);
        atomicAdd(b0 + 1, O[j][1]);
        atomicAdd(b1,     O[j][2]);
        atomicAdd(b1 + 1, O[j][3]);
    }
}

// ---- sparse bias corrections (fp32-exact) ----
__global__ void k_corr(const float* __restrict__ mag, const float* __restrict__ phase) {
    int w = (blockIdx.x * blockDim.x + threadIdx.x) >> 5;
    int lane = threadIdx.x & 31;
    if (w >= g_ne) return;
    int src = g_csrc[w], dst = g_cdst[w];
    float bias = g_cbias[w];

    const float4* Gs = (const float4*)(g_G + src * 128);
    const float4* Gd = (const float4*)(g_G + dst * 128);
    float4 a = Gs[lane], q = Gd[lane];
    float s = a.x * q.x + a.y * q.y + a.z * q.z + a.w * q.w;
    #pragma unroll
    for (int off = 16; off; off >>= 1) s += __shfl_xor_sync(0xffffffffu, s, off);

    float delta = __expf(s) * expm1f(bias);
    if (lane == 0) atomicAdd(&g_rsum[src], delta);
    atomicAdd(&g_accm[src * 64 + lane],      delta * mag[dst * 64 + lane]);
    atomicAdd(&g_accm[src * 64 + lane + 32], delta * mag[dst * 64 + lane + 32]);
    atomicAdd(&g_accp[src * 64 + lane],      delta * phase[dst * 64 + lane]);
    atomicAdd(&g_accp[src * 64 + lane + 32], delta * phase[dst * 64 + lane + 32]);
}

__global__ void k_norm(float* __restrict__ out) {
    int idx = blockIdx.x * blockDim.x + threadIdx.x;
    if (idx >= NN * DD) return;
    float inv = 1.f / g_rsum[idx >> 6];
    out[idx]           = g_accm[idx] * inv;
    out[NN * DD + idx] = g_accp[idx] * inv;
}

extern "C" void kernel_launch(void* const* d_in, const int* in_sizes, int n_in,
                              void* d_out, int out_size) {
    const float* mag   = (const float*)d_in[0];
    const float* phase = (const float*)d_in[1];
    const void*  ei    = d_in[2];
    const float* ea    = (const float*)d_in[3];
    const float* W     = (const float*)d_in[4];
    const float* b     = (const float*)d_in[5];
    float* out = (float*)d_out;

    cudaFuncSetAttribute(k_attn, cudaFuncAttributeMaxDynamicSharedMemorySize, SMEMSZ);

    k_detect<<<1, 32>>>((const unsigned*)ei);
    k_wsum<<<1, 64>>>(W, b);
    k_prep<<<(NN * DD + 255) / 256, 256>>>(mag, phase);
    dim3 gv(NN / 32, 4);
    k_prepv<<<gv, 256>>>(mag, phase);
    k_clear<<<(HSIZE + 255) / 256, 256>>>();
    k_edge<<<(EE + 255) / 256, 256>>>(ei, ea);
    k_compact<<<(HSIZE + 255) / 256, 256>>>();
    k_attn<<<128, 256, SMEMSZ>>>();
    k_corr<<<EE / 8, 256>>>(mag, phase);
    k_norm<<<(NN * DD + 255) / 256, 256>>>(out);
}

// round 6
// speedup vs baseline: 5.6574x; 1.4099x over previous
#include <cuda_runtime.h>
#include <cuda_bf16.h>
#include <cuda_fp16.h>
#include <math.h>

#define NN 8192
#define DD 64
#define EE 262144
#define HSIZE (1u << 20)
#define HMASK (HSIZE - 1u)
#define HEMPTY 0xFFFFFFFFFFFFFFFFull

// ===================== base-ISA tensor primitives =====================
#define MMA_BF16(C, A, B0, B1) \
    asm volatile("mma.sync.aligned.m16n8k16.row.col.f32.bf16.bf16.f32 " \
        "{%0,%1,%2,%3}, {%4,%5,%6,%7}, {%8,%9}, {%0,%1,%2,%3};" \
        : "+f"((C)[0]), "+f"((C)[1]), "+f"((C)[2]), "+f"((C)[3]) \
        : "r"((A)[0]), "r"((A)[1]), "r"((A)[2]), "r"((A)[3]), "r"(B0), "r"(B1))

#define MMA_F16(C, A, B0, B1) \
    asm volatile("mma.sync.aligned.m16n8k16.row.col.f32.f16.f16.f32 " \
        "{%0,%1,%2,%3}, {%4,%5,%6,%7}, {%8,%9}, {%0,%1,%2,%3};" \
        : "+f"((C)[0]), "+f"((C)[1]), "+f"((C)[2]), "+f"((C)[3]) \
        : "r"((A)[0]), "r"((A)[1]), "r"((A)[2]), "r"((A)[3]), "r"(B0), "r"(B1))

#define LDSM4(R, addr) \
    asm volatile("ldmatrix.sync.aligned.m8n8.x4.shared.b16 {%0,%1,%2,%3}, [%4];" \
        : "=r"((R)[0]), "=r"((R)[1]), "=r"((R)[2]), "=r"((R)[3]) : "r"(addr))

#define CPA16(dst, src) \
    asm volatile("cp.async.cg.shared.global [%0], [%1], 16;" :: "r"(dst), "l"(src))
#define CP_COMMIT() asm volatile("cp.async.commit_group;" ::: "memory")
#define CP_WAIT0()  asm volatile("cp.async.wait_group 0;" ::: "memory")

__device__ __forceinline__ unsigned pack_bf16x2(float lo, float hi) {
    unsigned r;
    asm("cvt.rn.bf16x2.f32 %0, %1, %2;" : "=r"(r) : "f"(hi), "f"(lo));
    return r;
}

// ===================== static device scratch =====================
__device__ float g_G[NN * 128];                 // fp32 (for k_corr)
__device__ __half g_Gh[NN * 128];               // fp16 G (S matmul)
__device__ __nv_bfloat16 g_Vth[128 * NN];       // V^T hi
__device__ __nv_bfloat16 g_Vtl[128 * NN];       // V^T lo
__device__ float g_rsum[NN];
__device__ float g_accm[NN * DD];
__device__ float g_accp[NN * DD];
__device__ unsigned long long g_hash[HSIZE];
__device__ float g_escore[EE];
__device__ int   g_ne;
__device__ int   g_csrc[EE];
__device__ int   g_cdst[EE];
__device__ float g_cbias[EE];
__device__ float g_wsum4[4];
__device__ float g_bsum;
__device__ int   g_idx64;

// ===================== small kernels =====================
__global__ void k_detect(const unsigned* __restrict__ p) {
    if (threadIdx.x == 0) {
        int all0 = 1;
        #pragma unroll
        for (int i = 1; i < 64; i += 2)
            if (p[i] != 0u) all0 = 0;
        g_idx64 = all0;
    }
}

__global__ void k_wsum(const float* __restrict__ W, const float* __restrict__ b) {
    __shared__ float red[5][64];
    int t = threadIdx.x;
    red[0][t] = W[t * 4 + 0];
    red[1][t] = W[t * 4 + 1];
    red[2][t] = W[t * 4 + 2];
    red[3][t] = W[t * 4 + 3];
    red[4][t] = b[t];
    __syncthreads();
    if (t < 5) {
        float s = 0.f;
        #pragma unroll
        for (int i = 0; i < 64; i++) s += red[t][i];
        if (t < 4) g_wsum4[t] = s;
        else       g_bsum = s;
    }
}

__global__ void k_prep(const float* __restrict__ mag, const float* __restrict__ phase) {
    int idx = blockIdx.x * blockDim.x + threadIdx.x;
    if (idx >= NN * DD) return;
    int i = idx >> 6, d = idx & 63;
    float m = mag[idx], ph = phase[idx];
    float sv, cv;
    sincosf(ph, &sv, &cv);
    float gc = m * cv, gs = m * sv;
    g_G[i * 128 + d]      = gc;
    g_G[i * 128 + 64 + d] = gs;
    g_Gh[i * 128 + d]      = __float2half(gc);
    g_Gh[i * 128 + 64 + d] = __float2half(gs);
}

// transpose [k][d] -> Vt[d][k] with bf16 hi/lo split (32x32 tiles)
__global__ void k_prepv(const float* __restrict__ mag, const float* __restrict__ phase) {
    __shared__ float t[32][33];
    int k0 = blockIdx.x * 32;
    int d0 = blockIdx.y * 32;
    int tx = threadIdx.x & 31, ty = threadIdx.x >> 5;
    const float* src = (d0 < 64) ? mag : phase;
    int dcol = (d0 < 64) ? d0 : d0 - 64;
    #pragma unroll
    for (int r = 0; r < 4; r++) {
        int k = k0 + ty + r * 8;
        t[ty + r * 8][tx] = src[k * 64 + dcol + tx];
    }
    __syncthreads();
    #pragma unroll
    for (int r = 0; r < 4; r++) {
        int d = d0 + ty + r * 8;
        float v = t[tx][ty + r * 8];
        __nv_bfloat16 h = __float2bfloat16(v);
        g_Vth[d * NN + k0 + tx] = h;
        g_Vtl[d * NN + k0 + tx] = __float2bfloat16(v - __bfloat162float(h));
    }
}

__global__ void k_clear() {
    unsigned idx = blockIdx.x * blockDim.x + threadIdx.x;
    if (idx < HSIZE) g_hash[idx] = HEMPTY;
    if (idx < NN * DD) { g_accm[idx] = 0.f; g_accp[idx] = 0.f; }
    if (idx < NN) g_rsum[idx] = 0.f;
    if (idx == 0) g_ne = 0;
}

// ---- edge scores + lock-free dedupe (last edge index wins, JAX scatter-set order) ----
__global__ void k_edge(const void* __restrict__ eiv, const float* __restrict__ ea) {
    int e = blockIdx.x * blockDim.x + threadIdx.x;
    if (e >= EE) return;
    int src, dst;
    if (g_idx64) {
        const long long* ei = (const long long*)eiv;
        src = (int)ei[e];
        dst = (int)ei[EE + e];
    } else {
        const int* ei = (const int*)eiv;
        src = ei[e];
        dst = ei[EE + e];
    }
    src &= 8191; dst &= 8191;

    float score = ea[4 * e + 0] * g_wsum4[0] + ea[4 * e + 1] * g_wsum4[1]
                + ea[4 * e + 2] * g_wsum4[2] + ea[4 * e + 3] * g_wsum4[3] + g_bsum;
    g_escore[e] = score;

    unsigned key = ((unsigned)src << 13) | (unsigned)dst;
    unsigned long long entry = ((unsigned long long)key << 32) | (unsigned)e;
    unsigned h = key * 0x9E3779B1u;
    h ^= h >> 15;
    h &= HMASK;
    for (;;) {
        unsigned long long cur = g_hash[h];
        if (cur == HEMPTY) {
            unsigned long long prev = atomicCAS(&g_hash[h], HEMPTY, entry);
            if (prev == HEMPTY) break;
            cur = prev;
        }
        if ((unsigned)(cur >> 32) == key) {
            atomicMax(&g_hash[h], entry);
            break;
        }
        h = (h + 1) & HMASK;
    }
}

__global__ void k_compact() {
    unsigned idx = blockIdx.x * blockDim.x + threadIdx.x;
    if (idx >= HSIZE) return;
    unsigned long long cur = g_hash[idx];
    if (cur == HEMPTY) return;
    unsigned key = (unsigned)(cur >> 32);
    unsigned e   = (unsigned)(cur & 0xFFFFFFFFu);
    int pos = atomicAdd(&g_ne, 1);
    g_csrc[pos]  = (int)(key >> 13);
    g_cdst[pos]  = (int)(key & 8191u);
    g_cbias[pos] = g_escore[e];
}

// ===================== mma.sync flash attention =====================
// grid=128: qb = bid>>1 (128 q rows), ks = bid&1 (split-K half of 4096 keys)
#define QSTR 272
#define VSTR 144
#define SQH  0
#define BUF0 34816
#define BUFS 54272
#define KH_O 0
#define VH_O 17408
#define VL_O 35840
#define SMEMSZ (BUF0 + 2 * BUFS)   // 143360
#define NITER 64

__global__ void __launch_bounds__(256, 1)
k_attn() {
    extern __shared__ __align__(1024) char smem[];
    unsigned sb;
    asm("{ .reg .u64 t; cvta.to.shared.u64 t, %1; cvt.u32.u64 %0, t; }"
        : "=r"(sb) : "l"(smem));

    const int tid = threadIdx.x;
    const int lane = tid & 31;
    const int wid = tid >> 5;
    const int qb = blockIdx.x >> 1;
    const int ks = blockIdx.x & 1;
    const int m0 = wid * 16;

    // ---- prologue: Q tile (fp16) via cp.async ----
    {
        const __half* ghq = g_Gh + (qb * 128) * 128;
        for (int i = tid; i < 2048; i += 256) {
            int r = i >> 4, c = i & 15;
            CPA16(sb + SQH + r * QSTR + c * 16, (const char*)(ghq + r * 128 + c * 8));
        }
    }
    // ---- tile 0 K/V ----
    {
        int kbase = ks * 4096;
        unsigned bo = sb + BUF0;
        for (int i = tid; i < 1024; i += 256) {
            int r = i >> 4, c = i & 15;
            CPA16(bo + KH_O + r * QSTR + c * 16, (const char*)(g_Gh + (kbase + r) * 128 + c * 8));
        }
        for (int i = tid; i < 1024; i += 256) {
            int d = i >> 3, c = i & 7;
            CPA16(bo + VH_O + d * VSTR + c * 16, (const char*)(g_Vth + d * NN + kbase + c * 8));
            CPA16(bo + VL_O + d * VSTR + c * 16, (const char*)(g_Vtl + d * NN + kbase + c * 8));
        }
    }
    CP_COMMIT();
    CP_WAIT0();
    __syncthreads();

    const unsigned aoff = (unsigned)(m0 + (lane & 15)) * QSTR + (unsigned)(lane >> 4) * 16;
    const unsigned brow = (unsigned)((lane & 7) + ((lane >> 4) << 3));
    const unsigned bc16 = (unsigned)((lane >> 3) & 1) * 16;
    const unsigned kboff = brow * QSTR + bc16;
    const unsigned vboff = brow * VSTR + bc16;

    float O[16][4];
    #pragma unroll
    for (int j = 0; j < 16; j++)
        #pragma unroll
        for (int i = 0; i < 4; i++) O[j][i] = 0.f;
    float rs_lo = 0.f, rs_hi = 0.f;

    for (int it = 0; it < NITER; it++) {
        unsigned cur = sb + BUF0 + (unsigned)(it & 1) * BUFS;

        // prefetch next tile
        if (it + 1 < NITER) {
            int kbase = ks * 4096 + (it + 1) * 64;
            unsigned bo = sb + BUF0 + (unsigned)((it + 1) & 1) * BUFS;
            for (int i = tid; i < 1024; i += 256) {
                int r = i >> 4, c = i & 15;
                CPA16(bo + KH_O + r * QSTR + c * 16, (const char*)(g_Gh + (kbase + r) * 128 + c * 8));
            }
            for (int i = tid; i < 1024; i += 256) {
                int d = i >> 3, c = i & 7;
                CPA16(bo + VH_O + d * VSTR + c * 16, (const char*)(g_Vth + d * NN + kbase + c * 8));
                CPA16(bo + VL_O + d * VSTR + c * 16, (const char*)(g_Vtl + d * NN + kbase + c * 8));
            }
        }
        CP_COMMIT();

        // ---- S = Q.K^T single fp16 (m16 x n64, k=128) ----
        float S[8][4];
        #pragma unroll
        for (int j = 0; j < 8; j++)
            #pragma unroll
            for (int i = 0; i < 4; i++) S[j][i] = 0.f;

        #pragma unroll
        for (int kk = 0; kk < 8; kk++) {
            unsigned k2 = kk * 32;
            unsigned qh[4];
            LDSM4(qh, sb + SQH + aoff + k2);
            #pragma unroll
            for (int nt = 0; nt < 4; nt++) {
                unsigned kh[4];
                LDSM4(kh, cur + KH_O + (unsigned)(nt * 16) * QSTR + kboff + k2);
                MMA_F16(S[2 * nt],     qh, kh[0], kh[1]);
                MMA_F16(S[2 * nt + 1], qh, kh[2], kh[3]);
            }
        }

        // ---- P = exp(S) in bf16; rowsum over rounded P for exact normalization ----
        unsigned AH[4][4];
        #pragma unroll
        for (int j = 0; j < 8; j++) {
            float h0 = __bfloat162float(__float2bfloat16(__expf(S[j][0])));
            float h1 = __bfloat162float(__float2bfloat16(__expf(S[j][1])));
            float h2 = __bfloat162float(__float2bfloat16(__expf(S[j][2])));
            float h3 = __bfloat162float(__float2bfloat16(__expf(S[j][3])));
            rs_lo += h0 + h1;
            rs_hi += h2 + h3;
            int c = j >> 1, o = (j & 1) * 2;
            AH[c][o]     = pack_bf16x2(h0, h1);
            AH[c][o + 1] = pack_bf16x2(h2, h3);
        }

        // ---- O += P.(Vhi + Vlo)  (m16 x n128, k=64) ----
        #pragma unroll
        for (int c = 0; c < 4; c++) {
            unsigned k2 = c * 32;
            #pragma unroll
            for (int nt = 0; nt < 8; nt++) {
                unsigned vh[4], vl[4];
                unsigned nbase = (unsigned)(nt * 16) * VSTR;
                LDSM4(vh, cur + VH_O + nbase + vboff + k2);
                LDSM4(vl, cur + VL_O + nbase + vboff + k2);
                MMA_BF16(O[2 * nt],     AH[c], vh[0], vh[1]);
                MMA_BF16(O[2 * nt],     AH[c], vl[0], vl[1]);
                MMA_BF16(O[2 * nt + 1], AH[c], vh[2], vh[3]);
                MMA_BF16(O[2 * nt + 1], AH[c], vl[2], vl[3]);
            }
        }

        CP_WAIT0();
        __syncthreads();
    }

    // ---- rowsum reduce within quad, write ----
    rs_lo += __shfl_xor_sync(0xffffffffu, rs_lo, 1);
    rs_lo += __shfl_xor_sync(0xffffffffu, rs_lo, 2);
    rs_hi += __shfl_xor_sync(0xffffffffu, rs_hi, 1);
    rs_hi += __shfl_xor_sync(0xffffffffu, rs_hi, 2);
    int r0 = qb * 128 + m0 + (lane >> 2);
    if ((lane & 3) == 0) {
        atomicAdd(&g_rsum[r0], rs_lo);
        atomicAdd(&g_rsum[r0 + 8], rs_hi);
    }

    // ---- O writeback (split-K atomics) ----
    #pragma unroll
    for (int j = 0; j < 16; j++) {
        int n = 8 * j + 2 * (lane & 3);
        float* b0 = (n < 64) ? &g_accm[r0 * 64 + n] : &g_accp[r0 * 64 + n - 64];
        float* b1 = (n < 64) ? &g_accm[(r0 + 8) * 64 + n] : &g_accp[(r0 + 8) * 64 + n - 64];
        atomicAdd(b0,     O[j][0]);
        atomicAdd(b0 + 1, O[j][1]);
        atomicAdd(b1,     O[j][2]);
        atomicAdd(b1 + 1, O[j][3]);
    }
}

// ---- sparse bias corrections: one warp per deduped edge (fp32-exact) ----
__global__ void k_corr(const float* __restrict__ mag, const float* __restrict__ phase) {
    int w = (blockIdx.x * blockDim.x + threadIdx.x) >> 5;
    int lane = threadIdx.x & 31;
    if (w >= g_ne) return;
    int src = g_csrc[w], dst = g_cdst[w];
    float bias = g_cbias[w];

    const float4* Gs = (const float4*)(g_G + src * 128);
    const float4* Gd = (const float4*)(g_G + dst * 128);
    float4 a = Gs[lane], q = Gd[lane];
    float s = a.x * q.x + a.y * q.y + a.z * q.z + a.w * q.w;
    #pragma unroll
    for (int off = 16; off; off >>= 1) s += __shfl_xor_sync(0xffffffffu, s, off);

    float delta = __expf(s) * expm1f(bias);
    if (lane == 0) atomicAdd(&g_rsum[src], delta);
    atomicAdd(&g_accm[src * 64 + lane],      delta * mag[dst * 64 + lane]);
    atomicAdd(&g_accm[src * 64 + lane + 32], delta * mag[dst * 64 + lane + 32]);
    atomicAdd(&g_accp[src * 64 + lane],      delta * phase[dst * 64 + lane]);
    atomicAdd(&g_accp[src * 64 + lane + 32], delta * phase[dst * 64 + lane + 32]);
}

__global__ void k_norm(float* __restrict__ out) {
    int idx = blockIdx.x * blockDim.x + threadIdx.x;
    if (idx >= NN * DD) return;
    float inv = 1.f / g_rsum[idx >> 6];
    out[idx]           = g_accm[idx] * inv;
    out[NN * DD + idx] = g_accp[idx] * inv;
}

extern "C" void kernel_launch(void* const* d_in, const int* in_sizes, int n_in,
                              void* d_out, int out_size) {
    const float* mag   = (const float*)d_in[0];
    const float* phase = (const float*)d_in[1];
    const void*  ei    = d_in[2];
    const float* ea    = (const float*)d_in[3];
    const float* W     = (const float*)d_in[4];
    const float* b     = (const float*)d_in[5];
    float* out = (float*)d_out;

    cudaFuncSetAttribute(k_attn, cudaFuncAttributeMaxDynamicSharedMemorySize, SMEMSZ);

    k_detect<<<1, 32>>>((const unsigned*)ei);
    k_wsum<<<1, 64>>>(W, b);
    k_prep<<<(NN * DD + 255) / 256, 256>>>(mag, phase);
    dim3 gv(NN / 32, 4);
    k_prepv<<<gv, 256>>>(mag, phase);
    k_clear<<<(HSIZE + 255) / 256, 256>>>();
    k_edge<<<(EE + 255) / 256, 256>>>(ei, ea);
    k_compact<<<(HSIZE + 255) / 256, 256>>>();
    k_attn<<<128, 256, SMEMSZ>>>();
    k_corr<<<EE / 8, 256>>>(mag, phase);
    k_norm<<<(NN * DD + 255) / 256, 256>>>(out);
}

// round 7
// speedup vs baseline: 7.4085x; 1.3095x over previous
#include <cuda_runtime.h>
#include <cuda_bf16.h>
#include <cuda_fp16.h>
#include <math.h>

#define NN 8192
#define DD 64
#define EE 262144
#define HSIZE (1u << 19)
#define HMASK (HSIZE - 1u)
#define HEMPTY 0xFFFFFFFFFFFFFFFFull

// ===================== base-ISA tensor primitives =====================
#define MMA_BF16(C, A, B0, B1) \
    asm volatile("mma.sync.aligned.m16n8k16.row.col.f32.bf16.bf16.f32 " \
        "{%0,%1,%2,%3}, {%4,%5,%6,%7}, {%8,%9}, {%0,%1,%2,%3};" \
        : "+f"((C)[0]), "+f"((C)[1]), "+f"((C)[2]), "+f"((C)[3]) \
        : "r"((A)[0]), "r"((A)[1]), "r"((A)[2]), "r"((A)[3]), "r"(B0), "r"(B1))

#define MMA_F16(C, A, B0, B1) \
    asm volatile("mma.sync.aligned.m16n8k16.row.col.f32.f16.f16.f32 " \
        "{%0,%1,%2,%3}, {%4,%5,%6,%7}, {%8,%9}, {%0,%1,%2,%3};" \
        : "+f"((C)[0]), "+f"((C)[1]), "+f"((C)[2]), "+f"((C)[3]) \
        : "r"((A)[0]), "r"((A)[1]), "r"((A)[2]), "r"((A)[3]), "r"(B0), "r"(B1))

#define LDSM4(R, addr) \
    asm volatile("ldmatrix.sync.aligned.m8n8.x4.shared.b16 {%0,%1,%2,%3}, [%4];" \
        : "=r"((R)[0]), "=r"((R)[1]), "=r"((R)[2]), "=r"((R)[3]) : "r"(addr))

#define CPA16(dst, src) \
    asm volatile("cp.async.cg.shared.global [%0], [%1], 16;" :: "r"(dst), "l"(src))
#define CP_COMMIT() asm volatile("cp.async.commit_group;" ::: "memory")
#define CP_WAIT0()  asm volatile("cp.async.wait_group 0;" ::: "memory")

__device__ __forceinline__ unsigned pack_bf16x2(float lo, float hi) {
    unsigned r;
    asm("cvt.rn.bf16x2.f32 %0, %1, %2;" : "=r"(r) : "f"(hi), "f"(lo));
    return r;
}

// ===================== static device scratch =====================
__device__ float g_G[NN * 128];                 // fp32 (for k_corr)
__device__ __half g_Gh[NN * 128];               // fp16 G (S matmul)
__device__ __nv_bfloat16 g_Vth[128 * NN];       // V^T bf16 (PV matmul)
__device__ float g_rsum[NN];
__device__ float g_accm[NN * DD];
__device__ float g_accp[NN * DD];
__device__ unsigned long long g_hash[HSIZE];
__device__ float g_escore[EE];
__device__ int   g_ne;
__device__ int   g_csrc[EE];
__device__ int   g_cdst[EE];
__device__ float g_cbias[EE];
__device__ float g_wsum4[4];
__device__ float g_bsum;
__device__ int   g_idx64;

// ===================== small kernels =====================
__global__ void k_detect(const unsigned* __restrict__ p) {
    if (threadIdx.x == 0) {
        int all0 = 1;
        #pragma unroll
        for (int i = 1; i < 64; i += 2)
            if (p[i] != 0u) all0 = 0;
        g_idx64 = all0;
    }
}

__global__ void k_wsum(const float* __restrict__ W, const float* __restrict__ b) {
    __shared__ float red[5][64];
    int t = threadIdx.x;
    red[0][t] = W[t * 4 + 0];
    red[1][t] = W[t * 4 + 1];
    red[2][t] = W[t * 4 + 2];
    red[3][t] = W[t * 4 + 3];
    red[4][t] = b[t];
    __syncthreads();
    if (t < 5) {
        float s = 0.f;
        #pragma unroll
        for (int i = 0; i < 64; i++) s += red[t][i];
        if (t < 4) g_wsum4[t] = s;
        else       g_bsum = s;
    }
}

__global__ void k_prep(const float* __restrict__ mag, const float* __restrict__ phase) {
    int idx = blockIdx.x * blockDim.x + threadIdx.x;
    if (idx >= NN * DD) return;
    int i = idx >> 6, d = idx & 63;
    float m = mag[idx], ph = phase[idx];
    float sv, cv;
    sincosf(ph, &sv, &cv);
    float gc = m * cv, gs = m * sv;
    g_G[i * 128 + d]      = gc;
    g_G[i * 128 + 64 + d] = gs;
    g_Gh[i * 128 + d]      = __float2half(gc);
    g_Gh[i * 128 + 64 + d] = __float2half(gs);
}

// transpose [k][d] -> Vt[d][k] bf16 (32x32 tiles)
__global__ void k_prepv(const float* __restrict__ mag, const float* __restrict__ phase) {
    __shared__ float t[32][33];
    int k0 = blockIdx.x * 32;
    int d0 = blockIdx.y * 32;
    int tx = threadIdx.x & 31, ty = threadIdx.x >> 5;
    const float* src = (d0 < 64) ? mag : phase;
    int dcol = (d0 < 64) ? d0 : d0 - 64;
    #pragma unroll
    for (int r = 0; r < 4; r++) {
        int k = k0 + ty + r * 8;
        t[ty + r * 8][tx] = src[k * 64 + dcol + tx];
    }
    __syncthreads();
    #pragma unroll
    for (int r = 0; r < 4; r++) {
        int d = d0 + ty + r * 8;
        g_Vth[d * NN + k0 + tx] = __float2bfloat16(t[tx][ty + r * 8]);
    }
}

__global__ void k_clear() {
    unsigned idx = blockIdx.x * blockDim.x + threadIdx.x;
    if (idx < HSIZE) g_hash[idx] = HEMPTY;
    if (idx < NN * DD) { g_accm[idx] = 0.f; g_accp[idx] = 0.f; }
    if (idx < NN) g_rsum[idx] = 0.f;
    if (idx == 0) g_ne = 0;
}

// ---- edge scores + lock-free dedupe (last edge index wins) ----
__global__ void k_edge(const void* __restrict__ eiv, const float* __restrict__ ea) {
    int e = blockIdx.x * blockDim.x + threadIdx.x;
    if (e >= EE) return;
    int src, dst;
    if (g_idx64) {
        const long long* ei = (const long long*)eiv;
        src = (int)ei[e];
        dst = (int)ei[EE + e];
    } else {
        const int* ei = (const int*)eiv;
        src = ei[e];
        dst = ei[EE + e];
    }
    src &= 8191; dst &= 8191;

    float score = ea[4 * e + 0] * g_wsum4[0] + ea[4 * e + 1] * g_wsum4[1]
                + ea[4 * e + 2] * g_wsum4[2] + ea[4 * e + 3] * g_wsum4[3] + g_bsum;
    g_escore[e] = score;

    unsigned key = ((unsigned)src << 13) | (unsigned)dst;
    unsigned long long entry = ((unsigned long long)key << 32) | (unsigned)e;
    unsigned h = key * 0x9E3779B1u;
    h ^= h >> 15;
    h &= HMASK;
    for (;;) {
        unsigned long long cur = g_hash[h];
        if (cur == HEMPTY) {
            unsigned long long prev = atomicCAS(&g_hash[h], HEMPTY, entry);
            if (prev == HEMPTY) break;
            cur = prev;
        }
        if ((unsigned)(cur >> 32) == key) {
            atomicMax(&g_hash[h], entry);
            break;
        }
        h = (h + 1) & HMASK;
    }
}

__global__ void k_compact() {
    unsigned idx = blockIdx.x * blockDim.x + threadIdx.x;
    if (idx >= HSIZE) return;
    unsigned long long cur = g_hash[idx];
    if (cur == HEMPTY) return;
    unsigned key = (unsigned)(cur >> 32);
    unsigned e   = (unsigned)(cur & 0xFFFFFFFFu);
    int pos = atomicAdd(&g_ne, 1);
    g_csrc[pos]  = (int)(key >> 13);
    g_cdst[pos]  = (int)(key & 8191u);
    g_cbias[pos] = g_escore[e];
}

// ===================== mma.sync flash attention =====================
// grid=128: qb = bid>>1 (128 q rows), ks = bid&1 (split-K half of 4096 keys)
#define QSTR 272
#define VSTR 144
#define SQH  0
#define BUF0 34816
#define BUFS 35840
#define KH_O 0
#define VH_O 17408
#define SMEMSZ (BUF0 + 2 * BUFS)   // 106496
#define NITER 64

__global__ void __launch_bounds__(256, 1)
k_attn() {
    extern __shared__ __align__(1024) char smem[];
    unsigned sb;
    asm("{ .reg .u64 t; cvta.to.shared.u64 t, %1; cvt.u32.u64 %0, t; }"
        : "=r"(sb) : "l"(smem));

    const int tid = threadIdx.x;
    const int lane = tid & 31;
    const int wid = tid >> 5;
    const int qb = blockIdx.x >> 1;
    const int ks = blockIdx.x & 1;
    const int m0 = wid * 16;

    // ---- prologue: Q tile (fp16) via cp.async ----
    {
        const __half* ghq = g_Gh + (qb * 128) * 128;
        for (int i = tid; i < 2048; i += 256) {
            int r = i >> 4, c = i & 15;
            CPA16(sb + SQH + r * QSTR + c * 16, (const char*)(ghq + r * 128 + c * 8));
        }
    }
    // ---- tile 0 K/V ----
    {
        int kbase = ks * 4096;
        unsigned bo = sb + BUF0;
        for (int i = tid; i < 1024; i += 256) {
            int r = i >> 4, c = i & 15;
            CPA16(bo + KH_O + r * QSTR + c * 16, (const char*)(g_Gh + (kbase + r) * 128 + c * 8));
        }
        for (int i = tid; i < 1024; i += 256) {
            int d = i >> 3, c = i & 7;
            CPA16(bo + VH_O + d * VSTR + c * 16, (const char*)(g_Vth + d * NN + kbase + c * 8));
        }
    }
    CP_COMMIT();
    CP_WAIT0();
    __syncthreads();

    const unsigned aoff = (unsigned)(m0 + (lane & 15)) * QSTR + (unsigned)(lane >> 4) * 16;
    const unsigned brow = (unsigned)((lane & 7) + ((lane >> 4) << 3));
    const unsigned bc16 = (unsigned)((lane >> 3) & 1) * 16;
    const unsigned kboff = brow * QSTR + bc16;
    const unsigned vboff = brow * VSTR + bc16;

    // ---- Q fragments are loop-invariant: hoist into registers ----
    unsigned QF[8][4];
    #pragma unroll
    for (int kk = 0; kk < 8; kk++)
        LDSM4(QF[kk], sb + SQH + aoff + (unsigned)(kk * 32));

    float O[16][4];
    #pragma unroll
    for (int j = 0; j < 16; j++)
        #pragma unroll
        for (int i = 0; i < 4; i++) O[j][i] = 0.f;
    float rs_lo = 0.f, rs_hi = 0.f;

    for (int it = 0; it < NITER; it++) {
        unsigned cur = sb + BUF0 + (unsigned)(it & 1) * BUFS;

        // prefetch next tile
        if (it + 1 < NITER) {
            int kbase = ks * 4096 + (it + 1) * 64;
            unsigned bo = sb + BUF0 + (unsigned)((it + 1) & 1) * BUFS;
            for (int i = tid; i < 1024; i += 256) {
                int r = i >> 4, c = i & 15;
                CPA16(bo + KH_O + r * QSTR + c * 16, (const char*)(g_Gh + (kbase + r) * 128 + c * 8));
            }
            for (int i = tid; i < 1024; i += 256) {
                int d = i >> 3, c = i & 7;
                CPA16(bo + VH_O + d * VSTR + c * 16, (const char*)(g_Vth + d * NN + kbase + c * 8));
            }
        }
        CP_COMMIT();

        // ---- S = Q.K^T single fp16 (m16 x n64, k=128) ----
        float S[8][4];
        #pragma unroll
        for (int j = 0; j < 8; j++)
            #pragma unroll
            for (int i = 0; i < 4; i++) S[j][i] = 0.f;

        #pragma unroll
        for (int kk = 0; kk < 8; kk++) {
            unsigned k2 = kk * 32;
            #pragma unroll
            for (int nt = 0; nt < 4; nt++) {
                unsigned kh[4];
                LDSM4(kh, cur + KH_O + (unsigned)(nt * 16) * QSTR + kboff + k2);
                MMA_F16(S[2 * nt],     QF[kk], kh[0], kh[1]);
                MMA_F16(S[2 * nt + 1], QF[kk], kh[2], kh[3]);
            }
        }

        // ---- P = exp(S) in bf16; rowsum over rounded P for exact normalization ----
        unsigned AH[4][4];
        #pragma unroll
        for (int j = 0; j < 8; j++) {
            float h0 = __bfloat162float(__float2bfloat16(__expf(S[j][0])));
            float h1 = __bfloat162float(__float2bfloat16(__expf(S[j][1])));
            float h2 = __bfloat162float(__float2bfloat16(__expf(S[j][2])));
            float h3 = __bfloat162float(__float2bfloat16(__expf(S[j][3])));
            rs_lo += h0 + h1;
            rs_hi += h2 + h3;
            int c = j >> 1, o = (j & 1) * 2;
            AH[c][o]     = pack_bf16x2(h0, h1);
            AH[c][o + 1] = pack_bf16x2(h2, h3);
        }

        // ---- O += P.Vhi  (m16 x n128, k=64); Vlo handled as diagonal fix in k_norm ----
        #pragma unroll
        for (int c = 0; c < 4; c++) {
            unsigned k2 = c * 32;
            #pragma unroll
            for (int nt = 0; nt < 8; nt++) {
                unsigned vh[4];
                LDSM4(vh, cur + VH_O + (unsigned)(nt * 16) * VSTR + vboff + k2);
                MMA_BF16(O[2 * nt],     AH[c], vh[0], vh[1]);
                MMA_BF16(O[2 * nt + 1], AH[c], vh[2], vh[3]);
            }
        }

        CP_WAIT0();
        __syncthreads();
    }

    // ---- rowsum reduce within quad, write ----
    rs_lo += __shfl_xor_sync(0xffffffffu, rs_lo, 1);
    rs_lo += __shfl_xor_sync(0xffffffffu, rs_lo, 2);
    rs_hi += __shfl_xor_sync(0xffffffffu, rs_hi, 1);
    rs_hi += __shfl_xor_sync(0xffffffffu, rs_hi, 2);
    int r0 = qb * 128 + m0 + (lane >> 2);
    if ((lane & 3) == 0) {
        atomicAdd(&g_rsum[r0], rs_lo);
        atomicAdd(&g_rsum[r0 + 8], rs_hi);
    }

    // ---- O writeback (split-K atomics) ----
    #pragma unroll
    for (int j = 0; j < 16; j++) {
        int n = 8 * j + 2 * (lane & 3);
        float* b0 = (n < 64) ? &g_accm[r0 * 64 + n] : &g_accp[r0 * 64 + n - 64];
        float* b1 = (n < 64) ? &g_accm[(r0 + 8) * 64 + n] : &g_accp[(r0 + 8) * 64 + n - 64];
        atomicAdd(b0,     O[j][0]);
        atomicAdd(b0 + 1, O[j][1]);
        atomicAdd(b1,     O[j][2]);
        atomicAdd(b1 + 1, O[j][3]);
    }
}

// ---- sparse bias corrections: one warp per deduped edge (fp32-exact) ----
__global__ void k_corr(const float* __restrict__ mag, const float* __restrict__ phase) {
    int w = (blockIdx.x * blockDim.x + threadIdx.x) >> 5;
    int lane = threadIdx.x & 31;
    if (w >= g_ne) return;
    int src = g_csrc[w], dst = g_cdst[w];
    float bias = g_cbias[w];

    const float4* Gs = (const float4*)(g_G + src * 128);
    const float4* Gd = (const float4*)(g_G + dst * 128);
    float4 a = Gs[lane], q = Gd[lane];
    float s = a.x * q.x + a.y * q.y + a.z * q.z + a.w * q.w;
    #pragma unroll
    for (int off = 16; off; off >>= 1) s += __shfl_xor_sync(0xffffffffu, s, off);

    float delta = __expf(s) * expm1f(bias);
    if (lane == 0) atomicAdd(&g_rsum[src], delta);
    atomicAdd(&g_accm[src * 64 + lane],      delta * mag[dst * 64 + lane]);
    atomicAdd(&g_accm[src * 64 + lane + 32], delta * mag[dst * 64 + lane + 32]);
    atomicAdd(&g_accp[src * 64 + lane],      delta * phase[dst * 64 + lane]);
    atomicAdd(&g_accp[src * 64 + lane + 32], delta * phase[dst * 64 + lane + 32]);
}

// ---- normalize + diagonal Vlo correction:
//      true O = P.Vhi + Sum_k p_k vlo_k ~= P.Vhi + exp(||mag_i||^2) * vlo_i  ----
__global__ void k_norm(const float* __restrict__ mag, const float* __restrict__ phase,
                       float* __restrict__ out) {
    int tid = threadIdx.x;             // 256 = 4 rows x 64
    int sub = tid >> 6;
    int d = tid & 63;
    int row = blockIdx.x * 4 + sub;
    float m = mag[row * 64 + d];
    float p = phase[row * 64 + d];

    float s = m * m;
    #pragma unroll
    for (int o = 16; o; o >>= 1) s += __shfl_xor_sync(0xffffffffu, s, o);
    __shared__ float sred[8];
    if ((tid & 31) == 0) sred[tid >> 5] = s;
    __syncthreads();
    float pii = __expf(sred[sub * 2] + sred[sub * 2 + 1]);   // exp(||G_i||^2), diag score exact

    float inv = 1.f / g_rsum[row];
    float vlom = m - __bfloat162float(__float2bfloat16(m));
    float vlop = p - __bfloat162float(__float2bfloat16(p));
    out[row * 64 + d]           = (g_accm[row * 64 + d] + pii * vlom) * inv;
    out[NN * DD + row * 64 + d] = (g_accp[row * 64 + d] + pii * vlop) * inv;
}

extern "C" void kernel_launch(void* const* d_in, const int* in_sizes, int n_in,
                              void* d_out, int out_size) {
    const float* mag   = (const float*)d_in[0];
    const float* phase = (const float*)d_in[1];
    const void*  ei    = d_in[2];
    const float* ea    = (const float*)d_in[3];
    const float* W     = (const float*)d_in[4];
    const float* b     = (const float*)d_in[5];
    float* out = (float*)d_out;

    cudaFuncSetAttribute(k_attn, cudaFuncAttributeMaxDynamicSharedMemorySize, SMEMSZ);

    k_detect<<<1, 32>>>((const unsigned*)ei);
    k_wsum<<<1, 64>>>(W, b);
    k_prep<<<(NN * DD + 255) / 256, 256>>>(mag, phase);
    dim3 gv(NN / 32, 4);
    k_prepv<<<gv, 256>>>(mag, phase);
    k_clear<<<(NN * DD + 255) / 256, 256>>>();
    k_edge<<<(EE + 255) / 256, 256>>>(ei, ea);
    k_compact<<<(HSIZE + 255) / 256, 256>>>();
    k_attn<<<128, 256, SMEMSZ>>>();
    k_corr<<<EE / 8, 256>>>(mag, phase);
    k_norm<<<NN / 4, 256>>>(mag, phase, out);
}

// round 10
// speedup vs baseline: 7.5245x; 1.0157x over previous
#include <cuda_runtime.h>
#include <cuda_bf16.h>
#include <cuda_fp16.h>
#include <math.h>

#define NN 8192
#define DD 64
#define EE 262144
#define HSIZE (1u << 19)
#define HMASK (HSIZE - 1u)
#define HEMPTY 0xFFFFFFFFFFFFFFFFull

// ===================== base-ISA tensor primitives =====================
#define MMA_BF16(C, A, B0, B1) \
    asm volatile("mma.sync.aligned.m16n8k16.row.col.f32.bf16.bf16.f32 " \
        "{%0,%1,%2,%3}, {%4,%5,%6,%7}, {%8,%9}, {%0,%1,%2,%3};" \
        : "+f"((C)[0]), "+f"((C)[1]), "+f"((C)[2]), "+f"((C)[3]) \
        : "r"((A)[0]), "r"((A)[1]), "r"((A)[2]), "r"((A)[3]), "r"(B0), "r"(B1))

#define MMA_F16(C, A, B0, B1) \
    asm volatile("mma.sync.aligned.m16n8k16.row.col.f32.f16.f16.f32 " \
        "{%0,%1,%2,%3}, {%4,%5,%6,%7}, {%8,%9}, {%0,%1,%2,%3};" \
        : "+f"((C)[0]), "+f"((C)[1]), "+f"((C)[2]), "+f"((C)[3]) \
        : "r"((A)[0]), "r"((A)[1]), "r"((A)[2]), "r"((A)[3]), "r"(B0), "r"(B1))

#define LDSM4(R, addr) \
    asm volatile("ldmatrix.sync.aligned.m8n8.x4.shared.b16 {%0,%1,%2,%3}, [%4];" \
        : "=r"((R)[0]), "=r"((R)[1]), "=r"((R)[2]), "=r"((R)[3]) : "r"(addr))

#define CPA16(dst, src) \
    asm volatile("cp.async.cg.shared.global [%0], [%1], 16;" :: "r"(dst), "l"(src))
#define CP_COMMIT() asm volatile("cp.async.commit_group;" ::: "memory")
#define CP_WAIT0()  asm volatile("cp.async.wait_group 0;" ::: "memory")

__device__ __forceinline__ unsigned pack_bf16x2(float lo, float hi) {
    unsigned r;
    asm("cvt.rn.bf16x2.f32 %0, %1, %2;" : "=r"(r) : "f"(hi), "f"(lo));
    return r;
}

// ===================== static device scratch =====================
__device__ float g_G[NN * 128];                 // fp32 G (k_corr exact scores)
__device__ __half g_Gh[NN * 128];               // fp16 G (S matmul)
__device__ __nv_bfloat16 g_Vth[128 * NN];       // V^T bf16 (PV matmul)
__device__ float g_ediag[NN];                   // exp(||mag_i||^2) = exact diag weight
__device__ float g_rsum[NN];
__device__ float g_accm[NN * DD];
__device__ float g_accp[NN * DD];
__device__ unsigned long long g_hash[HSIZE];
__device__ float g_escore[EE];
__device__ int   g_ne;
__device__ int   g_csrc[EE];
__device__ int   g_cdst[EE];
__device__ float g_cbias[EE];
__device__ float g_wsum4[4];
__device__ float g_bsum;
__device__ int   g_idx64;

// ===================== small kernels =====================
__global__ void k_detect(const unsigned* __restrict__ p) {
    if (threadIdx.x == 0) {
        int all0 = 1;
        #pragma unroll
        for (int i = 1; i < 64; i += 2)
            if (p[i] != 0u) all0 = 0;
        g_idx64 = all0;
    }
}

__global__ void k_wsum(const float* __restrict__ W, const float* __restrict__ b) {
    __shared__ float red[5][64];
    int t = threadIdx.x;
    red[0][t] = W[t * 4 + 0];
    red[1][t] = W[t * 4 + 1];
    red[2][t] = W[t * 4 + 2];
    red[3][t] = W[t * 4 + 3];
    red[4][t] = b[t];
    __syncthreads();
    if (t < 5) {
        float s = 0.f;
        #pragma unroll
        for (int i = 0; i < 64; i++) s += red[t][i];
        if (t < 4) g_wsum4[t] = s;
        else       g_bsum = s;
    }
}

__global__ void k_prep(const float* __restrict__ mag, const float* __restrict__ phase) {
    int idx = blockIdx.x * blockDim.x + threadIdx.x;
    if (idx >= NN * DD) return;
    int i = idx >> 6, d = idx & 63;
    float m = mag[idx], ph = phase[idx];
    float sv, cv;
    sincosf(ph, &sv, &cv);
    float gc = m * cv, gs = m * sv;
    g_G[i * 128 + d]      = gc;
    g_G[i * 128 + 64 + d] = gs;
    g_Gh[i * 128 + d]      = __float2half(gc);
    g_Gh[i * 128 + 64 + d] = __float2half(gs);
}

// transpose [k][d] -> Vt[d][k] bf16 (32x32 tiles)
__global__ void k_prepv(const float* __restrict__ mag, const float* __restrict__ phase) {
    __shared__ float t[32][33];
    int k0 = blockIdx.x * 32;
    int d0 = blockIdx.y * 32;
    int tx = threadIdx.x & 31, ty = threadIdx.x >> 5;
    const float* src = (d0 < 64) ? mag : phase;
    int dcol = (d0 < 64) ? d0 : d0 - 64;
    #pragma unroll
    for (int r = 0; r < 4; r++) {
        int k = k0 + ty + r * 8;
        t[ty + r * 8][tx] = src[k * 64 + dcol + tx];
    }
    __syncthreads();
    #pragma unroll
    for (int r = 0; r < 4; r++) {
        int d = d0 + ty + r * 8;
        g_Vth[d * NN + k0 + tx] = __float2bfloat16(t[tx][ty + r * 8]);
    }
}

// g_ediag[i] = exp(||mag_i||^2)  (exact diag score: cos^2+sin^2=1)
__global__ void k_diag(const float* __restrict__ mag) {
    int row = blockIdx.x * 8 + (threadIdx.x >> 5);
    int lane = threadIdx.x & 31;
    float2 a = *(const float2*)(mag + row * 64 + lane * 2);
    float s = a.x * a.x + a.y * a.y;
    #pragma unroll
    for (int o = 16; o; o >>= 1) s += __shfl_xor_sync(0xffffffffu, s, o);
    if (lane == 0) g_ediag[row] = __expf(s);
}

__global__ void k_clear() {
    unsigned idx = blockIdx.x * blockDim.x + threadIdx.x;
    if (idx < HSIZE) g_hash[idx] = HEMPTY;
    if (idx < NN * DD) { g_accm[idx] = 0.f; g_accp[idx] = 0.f; }
    if (idx < NN) g_rsum[idx] = 0.f;
    if (idx == 0) g_ne = 0;
}

// ---- edge scores + lock-free dedupe (last edge index wins) ----
__global__ void k_edge(const void* __restrict__ eiv, const float* __restrict__ ea) {
    int e = blockIdx.x * blockDim.x + threadIdx.x;
    if (e >= EE) return;
    int src, dst;
    if (g_idx64) {
        const long long* ei = (const long long*)eiv;
        src = (int)ei[e];
        dst = (int)ei[EE + e];
    } else {
        const int* ei = (const int*)eiv;
        src = ei[e];
        dst = ei[EE + e];
    }
    src &= 8191; dst &= 8191;

    float score = ea[4 * e + 0] * g_wsum4[0] + ea[4 * e + 1] * g_wsum4[1]
                + ea[4 * e + 2] * g_wsum4[2] + ea[4 * e + 3] * g_wsum4[3] + g_bsum;
    g_escore[e] = score;

    unsigned key = ((unsigned)src << 13) | (unsigned)dst;
    unsigned long long entry = ((unsigned long long)key << 32) | (unsigned)e;
    unsigned h = key * 0x9E3779B1u;
    h ^= h >> 15;
    h &= HMASK;
    for (;;) {
        unsigned long long cur = g_hash[h];
        if (cur == HEMPTY) {
            unsigned long long prev = atomicCAS(&g_hash[h], HEMPTY, entry);
            if (prev == HEMPTY) break;
            cur = prev;
        }
        if ((unsigned)(cur >> 32) == key) {
            atomicMax(&g_hash[h], entry);
            break;
        }
        h = (h + 1) & HMASK;
    }
}

__global__ void k_compact() {
    unsigned idx = blockIdx.x * blockDim.x + threadIdx.x;
    if (idx >= HSIZE) return;
    unsigned long long cur = g_hash[idx];
    if (cur == HEMPTY) return;
    unsigned key = (unsigned)(cur >> 32);
    unsigned e   = (unsigned)(cur & 0xFFFFFFFFu);
    int pos = atomicAdd(&g_ne, 1);
    g_csrc[pos]  = (int)(key >> 13);
    g_cdst[pos]  = (int)(key & 8191u);
    g_cbias[pos] = g_escore[e];
}

// ===================== mma.sync flash attention =====================
// grid=256: qb = bid>>2 (128 q rows), ks = bid&3 (split-K quarter = 2048 keys)
// 2 CTAs/SM (smem 104KB, <=128 regs/thread)
#define QSTR 272
#define VSTR 144
#define SQH  0
#define BUF0 34816
#define BUFS 35840
#define KH_O 0
#define VH_O 17408
#define SMEMSZ (BUF0 + 2 * BUFS)   // 106496
#define NITER 32

__global__ void __launch_bounds__(256, 2)
k_attn() {
    extern __shared__ __align__(1024) char smem[];
    unsigned sb;
    asm("{ .reg .u64 t; cvta.to.shared.u64 t, %1; cvt.u32.u64 %0, t; }"
        : "=r"(sb) : "l"(smem));

    const int tid = threadIdx.x;
    const int lane = tid & 31;
    const int wid = tid >> 5;
    const int qb = blockIdx.x >> 2;
    const int ks = blockIdx.x & 3;
    const int m0 = wid * 16;

    // ---- prologue: Q tile (fp16) via cp.async ----
    {
        const __half* ghq = g_Gh + (qb * 128) * 128;
        for (int i = tid; i < 2048; i += 256) {
            int r = i >> 4, c = i & 15;
            CPA16(sb + SQH + r * QSTR + c * 16, (const char*)(ghq + r * 128 + c * 8));
        }
    }
    // ---- tile 0 K/V ----
    {
        int kbase = ks * 2048;
        unsigned bo = sb + BUF0;
        for (int i = tid; i < 1024; i += 256) {
            int r = i >> 4, c = i & 15;
            CPA16(bo + KH_O + r * QSTR + c * 16, (const char*)(g_Gh + (kbase + r) * 128 + c * 8));
        }
        for (int i = tid; i < 1024; i += 256) {
            int d = i >> 3, c = i & 7;
            CPA16(bo + VH_O + d * VSTR + c * 16, (const char*)(g_Vth + d * NN + kbase + c * 8));
        }
    }
    CP_COMMIT();
    CP_WAIT0();
    __syncthreads();

    const unsigned aoff = (unsigned)(m0 + (lane & 15)) * QSTR + (unsigned)(lane >> 4) * 16;
    const unsigned brow = (unsigned)((lane & 7) + ((lane >> 4) << 3));
    const unsigned bc16 = (unsigned)((lane >> 3) & 1) * 16;
    const unsigned kboff = brow * QSTR + bc16;
    const unsigned vboff = brow * VSTR + bc16;

    float O[16][4];
    #pragma unroll
    for (int j = 0; j < 16; j++)
        #pragma unroll
        for (int i = 0; i < 4; i++) O[j][i] = 0.f;
    float rs_lo = 0.f, rs_hi = 0.f;

    for (int it = 0; it < NITER; it++) {
        unsigned cur = sb + BUF0 + (unsigned)(it & 1) * BUFS;

        // prefetch next tile
        if (it + 1 < NITER) {
            int kbase = ks * 2048 + (it + 1) * 64;
            unsigned bo = sb + BUF0 + (unsigned)((it + 1) & 1) * BUFS;
            for (int i = tid; i < 1024; i += 256) {
                int r = i >> 4, c = i & 15;
                CPA16(bo + KH_O + r * QSTR + c * 16, (const char*)(g_Gh + (kbase + r) * 128 + c * 8));
            }
            for (int i = tid; i < 1024; i += 256) {
                int d = i >> 3, c = i & 7;
                CPA16(bo + VH_O + d * VSTR + c * 16, (const char*)(g_Vth + d * NN + kbase + c * 8));
            }
        }
        CP_COMMIT();

        // ---- S = Q.K^T single fp16 (m16 x n64, k=128) ----
        float S[8][4];
        #pragma unroll
        for (int j = 0; j < 8; j++)
            #pragma unroll
            for (int i = 0; i < 4; i++) S[j][i] = 0.f;

        #pragma unroll
        for (int kk = 0; kk < 8; kk++) {
            unsigned k2 = kk * 32;
            unsigned qf[4];
            LDSM4(qf, sb + SQH + aoff + k2);
            #pragma unroll
            for (int nt = 0; nt < 4; nt++) {
                unsigned kh[4];
                LDSM4(kh, cur + KH_O + (unsigned)(nt * 16) * QSTR + kboff + k2);
                MMA_F16(S[2 * nt],     qf, kh[0], kh[1]);
                MMA_F16(S[2 * nt + 1], qf, kh[2], kh[3]);
            }
        }

        // ---- P = exp(S) packed to bf16; rowsum over the SAME rounded values ----
        unsigned AH[4][4];
        #pragma unroll
        for (int j = 0; j < 8; j++) {
            int c = j >> 1, o = (j & 1) * 2;
            unsigned p01 = pack_bf16x2(__expf(S[j][0]), __expf(S[j][1]));
            unsigned p23 = pack_bf16x2(__expf(S[j][2]), __expf(S[j][3]));
            AH[c][o]     = p01;
            AH[c][o + 1] = p23;
            rs_lo += __uint_as_float(p01 << 16) + __uint_as_float(p01 & 0xffff0000u);
            rs_hi += __uint_as_float(p23 << 16) + __uint_as_float(p23 & 0xffff0000u);
        }

        // ---- O += P.Vhi  (m16 x n128, k=64); Vlo handled as diagonal fix in k_norm ----
        #pragma unroll
        for (int c = 0; c < 4; c++) {
            unsigned k2 = c * 32;
            #pragma unroll
            for (int nt = 0; nt < 8; nt++) {
                unsigned vh[4];
                LDSM4(vh, cur + VH_O + (unsigned)(nt * 16) * VSTR + vboff + k2);
                MMA_BF16(O[2 * nt],     AH[c], vh[0], vh[1]);
                MMA_BF16(O[2 * nt + 1], AH[c], vh[2], vh[3]);
            }
        }

        CP_WAIT0();
        __syncthreads();
    }

    // ---- rowsum reduce within quad, write ----
    rs_lo += __shfl_xor_sync(0xffffffffu, rs_lo, 1);
    rs_lo += __shfl_xor_sync(0xffffffffu, rs_lo, 2);
    rs_hi += __shfl_xor_sync(0xffffffffu, rs_hi, 1);
    rs_hi += __shfl_xor_sync(0xffffffffu, rs_hi, 2);
    int r0 = qb * 128 + m0 + (lane >> 2);
    if ((lane & 3) == 0) {
        atomicAdd(&g_rsum[r0], rs_lo);
        atomicAdd(&g_rsum[r0 + 8], rs_hi);
    }

    // ---- O writeback (split-K atomics) ----
    #pragma unroll
    for (int j = 0; j < 16; j++) {
        int n = 8 * j + 2 * (lane & 3);
        float* b0 = (n < 64) ? &g_accm[r0 * 64 + n] : &g_accp[r0 * 64 + n - 64];
        float* b1 = (n < 64) ? &g_accm[(r0 + 8) * 64 + n] : &g_accp[(r0 + 8) * 64 + n - 64];
        atomicAdd(b0,     O[j][0]);
        atomicAdd(b0 + 1, O[j][1]);
        atomicAdd(b1,     O[j][2]);
        atomicAdd(b1 + 1, O[j][3]);
    }
}

// ---- sparse bias corrections: one warp per deduped edge, fp32-exact scores
//      (high-leverage cells must not inherit fp16 jitter — R9 lesson);
//      skip if |delta| <= 3e-7 * ediag_src <= 3e-7 * rowsum (err <= ~1e-5) ----
__global__ void k_corr(const float* __restrict__ mag, const float* __restrict__ phase) {
    int w = (blockIdx.x * blockDim.x + threadIdx.x) >> 5;
    int lane = threadIdx.x & 31;
    if (w >= g_ne) return;
    int src = g_csrc[w], dst = g_cdst[w];
    float bias = g_cbias[w];

    const float4* Gs = (const float4*)(g_G + src * 128);
    const float4* Gd = (const float4*)(g_G + dst * 128);
    float4 a = Gs[lane], q = Gd[lane];
    float s = a.x * q.x + a.y * q.y + a.z * q.z + a.w * q.w;
    #pragma unroll
    for (int off = 16; off; off >>= 1) s += __shfl_xor_sync(0xffffffffu, s, off);

    float delta = __expf(s) * expm1f(bias);
    if (fabsf(delta) <= 3e-7f * g_ediag[src]) return;   // uniform across warp

    if (lane == 0) atomicAdd(&g_rsum[src], delta);
    atomicAdd(&g_accm[src * 64 + lane],      delta * mag[dst * 64 + lane]);
    atomicAdd(&g_accm[src * 64 + lane + 32], delta * mag[dst * 64 + lane + 32]);
    atomicAdd(&g_accp[src * 64 + lane],      delta * phase[dst * 64 + lane]);
    atomicAdd(&g_accp[src * 64 + lane + 32], delta * phase[dst * 64 + lane + 32]);
}

// ---- normalize + diagonal Vlo correction ----
__global__ void k_norm(const float* __restrict__ mag, const float* __restrict__ phase,
                       float* __restrict__ out) {
    int tid = threadIdx.x;             // 256 = 4 rows x 64
    int sub = tid >> 6;
    int d = tid & 63;
    int row = blockIdx.x * 4 + sub;
    float m = mag[row * 64 + d];
    float p = phase[row * 64 + d];

    float pii = g_ediag[row];
    float inv = 1.f / g_rsum[row];
    float vlom = m - __bfloat162float(__float2bfloat16(m));
    float vlop = p - __bfloat162float(__float2bfloat16(p));
    out[row * 64 + d]           = (g_accm[row * 64 + d] + pii * vlom) * inv;
    out[NN * DD + row * 64 + d] = (g_accp[row * 64 + d] + pii * vlop) * inv;
}

extern "C" void kernel_launch(void* const* d_in, const int* in_sizes, int n_in,
                              void* d_out, int out_size) {
    const float* mag   = (const float*)d_in[0];
    const float* phase = (const float*)d_in[1];
    const void*  ei    = d_in[2];
    const float* ea    = (const float*)d_in[3];
    const float* W     = (const float*)d_in[4];
    const float* b     = (const float*)d_in[5];
    float* out = (float*)d_out;

    cudaFuncSetAttribute(k_attn, cudaFuncAttributeMaxDynamicSharedMemorySize, SMEMSZ);

    k_detect<<<1, 32>>>((const unsigned*)ei);
    k_wsum<<<1, 64>>>(W, b);
    k_prep<<<(NN * DD + 255) / 256, 256>>>(mag, phase);
    dim3 gv(NN / 32, 4);
    k_prepv<<<gv, 256>>>(mag, phase);
    k_diag<<<NN / 8, 256>>>(mag);
    k_clear<<<(NN * DD + 255) / 256, 256>>>();
    k_edge<<<(EE + 255) / 256, 256>>>(ei, ea);
    k_compact<<<(HSIZE + 255) / 256, 256>>>();
    k_attn<<<256, 256, SMEMSZ>>>();
    k_corr<<<EE / 8, 256>>>(mag, phase);
    k_norm<<<NN / 4, 256>>>(mag, phase, out);
}